// round 7
// baseline (speedup 1.0000x reference)
#include <cuda_runtime.h>
#include <cuda_bf16.h>
#include <cstdint>

// ============================================================================
// MoE layer collapses to: out = relu(x @ w1) @ w2
// (w1/w2 shared across experts, capacity=S so no drops, normalized top-2
//  gates sum to 1 -> Wg and dispatch/combine cancel exactly).
//
// NOTE: harness compiles through virtual arch compute_103 (no 'a'), so all
// sm_103a-specific instructions (tcgen05.*) are unavailable (ptxas error,
// round 5). This version uses only family-portable PTX: mma.sync.m16n8k16
// bf16 (sm_80+) and cp.async (sm_80+).
//
// Pipeline:
//   prep:  x -> bf16 hi/lo; w1,w2 -> transposed [N,K] bf16 hi/lo.
//   GEMM:  D[m][n] = sum_k A[m][k] B[n][k], 3x bf16 split accumulation
//          (hi*hi + lo*hi + hi*lo; dropped lo*lo ~2^-16 -> rel_err ~2e-5).
//          Tiles 128x128x32, cp.async double buffer, bf16 smem with
//          80B padded rows (conflict-free LDS.32 fragment loads, zero
//          conversions in the hot loop).
//   GEMM1: epilogue ReLU + split H to bf16 hi/lo (K-major = GEMM2 A format).
//   GEMM2: same tile (L2-traffic-optimal: 512MB vs 768MB at BM=64), fp32 out.
// ============================================================================

// ---------------- scratch (all bf16) ----------------
__device__ __nv_bfloat16 g_xh[2048 * 1024];
__device__ __nv_bfloat16 g_xl[2048 * 1024];
__device__ __nv_bfloat16 g_w1h[4096 * 1024];   // w1^T [DFF, D]
__device__ __nv_bfloat16 g_w1l[4096 * 1024];
__device__ __nv_bfloat16 g_w2h[1024 * 4096];   // w2^T [D, DFF]
__device__ __nv_bfloat16 g_w2l[1024 * 4096];
__device__ __nv_bfloat16 g_Hh[2048 * 4096];
__device__ __nv_bfloat16 g_Hl[2048 * 4096];

// ---------------- helpers ----------------
__device__ __forceinline__ void cp_async16(uint32_t s, const void* g) {
    asm volatile("cp.async.cg.shared.global [%0], [%1], 16;" :: "r"(s), "l"(g));
}
__device__ __forceinline__ void mma_bf16(float* acc, const uint32_t a[4],
                                         const uint32_t b[2]) {
    asm volatile(
        "mma.sync.aligned.m16n8k16.row.col.f32.bf16.bf16.f32 "
        "{%0,%1,%2,%3}, {%4,%5,%6,%7}, {%8,%9}, {%0,%1,%2,%3};"
        : "+f"(acc[0]), "+f"(acc[1]), "+f"(acc[2]), "+f"(acc[3])
        : "r"(a[0]), "r"(a[1]), "r"(a[2]), "r"(a[3]),
          "r"(b[0]), "r"(b[1]));
}

// ---------------- prep kernels ----------------
__global__ void split_f32(const float4* __restrict__ src,
                          __nv_bfloat162* __restrict__ hi,
                          __nv_bfloat162* __restrict__ lo, int n4) {
    int i = blockIdx.x * blockDim.x + threadIdx.x;
    if (i >= n4) return;
    float4 v = src[i];
    __nv_bfloat162 h0 = __floats2bfloat162_rn(v.x, v.y);
    __nv_bfloat162 h1 = __floats2bfloat162_rn(v.z, v.w);
    __nv_bfloat162 l0 = __floats2bfloat162_rn(v.x - __bfloat162float(h0.x),
                                              v.y - __bfloat162float(h0.y));
    __nv_bfloat162 l1 = __floats2bfloat162_rn(v.z - __bfloat162float(h1.x),
                                              v.w - __bfloat162float(h1.y));
    hi[2 * i] = h0; hi[2 * i + 1] = h1;
    lo[2 * i] = l0; lo[2 * i + 1] = l1;
}

// W [K,N] fp32 row-major -> T hi/lo [N,K] bf16 row-major
__global__ void transpose_split(const float* __restrict__ W,
                                __nv_bfloat16* __restrict__ Th,
                                __nv_bfloat16* __restrict__ Tl, int K, int N) {
    __shared__ float t[32][33];
    int x = blockIdx.x * 32 + threadIdx.x;   // N index
    int y = blockIdx.y * 32 + threadIdx.y;   // K index
    #pragma unroll
    for (int j = 0; j < 32; j += 8)
        t[threadIdx.y + j][threadIdx.x] = W[(size_t)(y + j) * N + x];
    __syncthreads();
    int x2 = blockIdx.y * 32 + threadIdx.x;  // K index (out)
    int y2 = blockIdx.x * 32 + threadIdx.y;  // N index (out)
    #pragma unroll
    for (int j = 0; j < 32; j += 8) {
        float v = t[threadIdx.x][threadIdx.y + j];
        __nv_bfloat16 h = __float2bfloat16_rn(v);
        __nv_bfloat16 l = __float2bfloat16_rn(v - __bfloat162float(h));
        Th[(size_t)(y2 + j) * K + x2] = h;
        Tl[(size_t)(y2 + j) * K + x2] = l;
    }
}

// ---------------- mma.sync GEMM ----------------
// D[m][n] = sum_k A[m][k]*B[n][k]; A [M,K], B [N,K], both bf16 hi/lo K-major.
// SPLIT_OUT: relu + write bf16 hi/lo (GEMM1). else: write fp32 (GEMM2).
template <bool SPLIT_OUT>
__global__ void __launch_bounds__(256)
gemm_hmma(const __nv_bfloat16* __restrict__ Ah, const __nv_bfloat16* __restrict__ Al,
          const __nv_bfloat16* __restrict__ Bh, const __nv_bfloat16* __restrict__ Bl,
          int K, int ldo,
          float* __restrict__ outF,
          __nv_bfloat16* __restrict__ outH, __nv_bfloat16* __restrict__ outL)
{
    constexpr int BM = 128;
    constexpr int BN = 128;
    constexpr int BK = 32;
    constexpr int ROWB = 80;                 // 64B data + 16B pad per row
    constexpr int A_BYTES = BM * ROWB;
    constexpr int B_BYTES = BN * ROWB;
    constexpr int STAGE = 2 * A_BYTES + 2 * B_BYTES;  // 40960
    constexpr int MI = 4;                    // m16 sub-tiles per warp (M)

    extern __shared__ char smem[];
    uint32_t sb;
    asm("{ .reg .u64 t; cvta.to.shared.u64 t, %1; cvt.u32.u64 %0, t; }"
        : "=r"(sb) : "l"(smem));
    const int tid  = threadIdx.x;
    const int lane = tid & 31;
    const int warp = tid >> 5;
    const int wm = (warp & 1) * 64;          // 2 warps in M (warp tile 64x32)
    const int wn = (warp >> 1) * 32;         // 4 warps in N
    const int brow = blockIdx.y * BM;
    const int bcol = blockIdx.x * BN;
    const int KT = K / BK;

    float acc[MI][4][4];
    #pragma unroll
    for (int mi = 0; mi < MI; ++mi)
        #pragma unroll
        for (int ni = 0; ni < 4; ++ni)
            #pragma unroll
            for (int r = 0; r < 4; ++r)
                acc[mi][ni][r] = 0.0f;

    auto load_stage = [&](int kt, int buf) {
        const int k0 = kt * BK;
        const uint32_t s0 = sb + buf * STAGE;
        // A: BM rows x 4 chunks of 16B (8 bf16) x {hi, lo}
        #pragma unroll
        for (int i = 0; i < (BM * 4) / 256; ++i) {
            int id = tid + i * 256;
            int r = id >> 2, c = id & 3;
            uint32_t so = (uint32_t)(r * ROWB + c * 16);
            size_t go = (size_t)(brow + r) * K + k0 + c * 8;
            cp_async16(s0 + so,           Ah + go);
            cp_async16(s0 + A_BYTES + so, Al + go);
        }
        // B: BN rows x 4 chunks x {hi, lo}
        #pragma unroll
        for (int i = 0; i < (BN * 4) / 256; ++i) {
            int id = tid + i * 256;
            int r = id >> 2, c = id & 3;
            uint32_t so = (uint32_t)(2 * A_BYTES + r * ROWB + c * 16);
            size_t go = (size_t)(bcol + r) * K + k0 + c * 8;
            cp_async16(s0 + so,           Bh + go);
            cp_async16(s0 + B_BYTES + so, Bl + go);
        }
        asm volatile("cp.async.commit_group;");
    };

    auto compute = [&](int buf) {
        const char* sa_h = smem + buf * STAGE;
        const char* sa_l = sa_h + A_BYTES;
        const char* sb_h = sa_h + 2 * A_BYTES;
        const char* sb_l = sb_h + B_BYTES;
        #pragma unroll
        for (int ks = 0; ks < 2; ++ks) {     // two k16 chunks per BK=32
            const int cbyte = (ks * 16 + (lane & 3) * 2) * 2;
            uint32_t ah[MI][4], al[MI][4];
            #pragma unroll
            for (int mi = 0; mi < MI; ++mi) {
                int base = (wm + mi * 16 + (lane >> 2)) * ROWB + cbyte;
                ah[mi][0] = *(const uint32_t*)(sa_h + base);
                ah[mi][1] = *(const uint32_t*)(sa_h + base + 8 * ROWB);
                ah[mi][2] = *(const uint32_t*)(sa_h + base + 16);
                ah[mi][3] = *(const uint32_t*)(sa_h + base + 8 * ROWB + 16);
                al[mi][0] = *(const uint32_t*)(sa_l + base);
                al[mi][1] = *(const uint32_t*)(sa_l + base + 8 * ROWB);
                al[mi][2] = *(const uint32_t*)(sa_l + base + 16);
                al[mi][3] = *(const uint32_t*)(sa_l + base + 8 * ROWB + 16);
            }
            uint32_t bh[4][2], bl[4][2];
            #pragma unroll
            for (int ni = 0; ni < 4; ++ni) {
                int base = (wn + ni * 8 + (lane >> 2)) * ROWB + cbyte;
                bh[ni][0] = *(const uint32_t*)(sb_h + base);
                bh[ni][1] = *(const uint32_t*)(sb_h + base + 16);
                bl[ni][0] = *(const uint32_t*)(sb_l + base);
                bl[ni][1] = *(const uint32_t*)(sb_l + base + 16);
            }
            #pragma unroll
            for (int mi = 0; mi < MI; ++mi) {
                #pragma unroll
                for (int ni = 0; ni < 4; ++ni) {
                    // 3x split: hi*hi + lo*hi + hi*lo (lo*lo dropped)
                    mma_bf16(acc[mi][ni], ah[mi], bh[ni]);
                    mma_bf16(acc[mi][ni], al[mi], bh[ni]);
                    mma_bf16(acc[mi][ni], ah[mi], bl[ni]);
                }
            }
        }
    };

    load_stage(0, 0);
    for (int kt = 0; kt < KT; ++kt) {
        const int buf = kt & 1;
        if (kt + 1 < KT) {
            load_stage(kt + 1, buf ^ 1);
            asm volatile("cp.async.wait_group 1;");
        } else {
            asm volatile("cp.async.wait_group 0;");
        }
        __syncthreads();
        compute(buf);
        __syncthreads();
    }

    // Epilogue
    #pragma unroll
    for (int mi = 0; mi < MI; ++mi) {
        int r0 = brow + wm + mi * 16 + (lane >> 2);
        #pragma unroll
        for (int ni = 0; ni < 4; ++ni) {
            int c0 = bcol + wn + ni * 8 + (lane & 3) * 2;
            if (SPLIT_OUT) {
                float v0 = fmaxf(acc[mi][ni][0], 0.0f);
                float v1 = fmaxf(acc[mi][ni][1], 0.0f);
                float v2 = fmaxf(acc[mi][ni][2], 0.0f);
                float v3 = fmaxf(acc[mi][ni][3], 0.0f);
                __nv_bfloat162 h01 = __floats2bfloat162_rn(v0, v1);
                __nv_bfloat162 l01 = __floats2bfloat162_rn(
                    v0 - __bfloat162float(h01.x), v1 - __bfloat162float(h01.y));
                __nv_bfloat162 h23 = __floats2bfloat162_rn(v2, v3);
                __nv_bfloat162 l23 = __floats2bfloat162_rn(
                    v2 - __bfloat162float(h23.x), v3 - __bfloat162float(h23.y));
                *(__nv_bfloat162*)(outH + (size_t)r0 * ldo + c0)       = h01;
                *(__nv_bfloat162*)(outL + (size_t)r0 * ldo + c0)       = l01;
                *(__nv_bfloat162*)(outH + (size_t)(r0 + 8) * ldo + c0) = h23;
                *(__nv_bfloat162*)(outL + (size_t)(r0 + 8) * ldo + c0) = l23;
            } else {
                float2 u0, u1;
                u0.x = acc[mi][ni][0]; u0.y = acc[mi][ni][1];
                u1.x = acc[mi][ni][2]; u1.y = acc[mi][ni][3];
                *(float2*)(outF + (size_t)r0 * ldo + c0)       = u0;
                *(float2*)(outF + (size_t)(r0 + 8) * ldo + c0) = u1;
            }
        }
    }
}

// ---------------- launch ----------------
extern "C" void kernel_launch(void* const* d_in, const int* in_sizes, int n_in,
                              void* d_out, int out_size) {
    (void)in_sizes; (void)n_in; (void)out_size;
    const float* x  = (const float*)d_in[0];
    // d_in[1] = Wg -- unused: routing cancels (normalized top-2 gates sum to 1)
    const float* w1 = (const float*)d_in[2];
    const float* w2 = (const float*)d_in[3];
    float* out = (float*)d_out;

    const int M = 2048, D = 1024, DFF = 4096;

    __nv_bfloat16 *xh, *xl, *w1h, *w1l, *w2h, *w2l, *Hh, *Hl;
    { void* p; cudaGetSymbolAddress(&p, g_xh);  xh  = (__nv_bfloat16*)p; }
    { void* p; cudaGetSymbolAddress(&p, g_xl);  xl  = (__nv_bfloat16*)p; }
    { void* p; cudaGetSymbolAddress(&p, g_w1h); w1h = (__nv_bfloat16*)p; }
    { void* p; cudaGetSymbolAddress(&p, g_w1l); w1l = (__nv_bfloat16*)p; }
    { void* p; cudaGetSymbolAddress(&p, g_w2h); w2h = (__nv_bfloat16*)p; }
    { void* p; cudaGetSymbolAddress(&p, g_w2l); w2l = (__nv_bfloat16*)p; }
    { void* p; cudaGetSymbolAddress(&p, g_Hh);  Hh  = (__nv_bfloat16*)p; }
    { void* p; cudaGetSymbolAddress(&p, g_Hl);  Hl  = (__nv_bfloat16*)p; }

    // smem: 2 stages x 40960 B
    const int smem = 2 * (2 * 128 * 80 + 2 * 128 * 80);  // 81920
    cudaFuncSetAttribute(gemm_hmma<true>,
                         cudaFuncAttributeMaxDynamicSharedMemorySize, smem);
    cudaFuncSetAttribute(gemm_hmma<false>,
                         cudaFuncAttributeMaxDynamicSharedMemorySize, smem);

    // prep: split x; transpose+split w1, w2
    split_f32<<<(M * D / 4 + 255) / 256, 256>>>(
        (const float4*)x, (__nv_bfloat162*)xh, (__nv_bfloat162*)xl, M * D / 4);
    transpose_split<<<dim3(DFF / 32, D / 32), dim3(32, 8)>>>(w1, w1h, w1l, D, DFF);
    transpose_split<<<dim3(D / 32, DFF / 32), dim3(32, 8)>>>(w2, w2h, w2l, DFF, D);

    // GEMM1: H = relu(x @ w1) -> bf16 hi/lo [2048, 4096], tiles 128x128
    gemm_hmma<true><<<dim3(DFF / 128, M / 128), 256, smem>>>(
        xh, xl, w1h, w1l, D, DFF, nullptr, Hh, Hl);
    // GEMM2: out = H @ w2 -> fp32 [2048, 1024], tiles 128x128
    gemm_hmma<false><<<dim3(D / 128, M / 128), 256, smem>>>(
        Hh, Hl, w2h, w2l, DFF, D, out, nullptr, nullptr);
}

// round 9
// speedup vs baseline: 1.3157x; 1.3157x over previous
#include <cuda_runtime.h>
#include <cuda_fp16.h>
#include <cstdint>

// ============================================================================
// MoE layer collapses to: out = relu(x @ w1) @ w2
// (w1/w2 shared across experts, capacity=S so no drops, normalized top-2
//  gates sum to 1 -> Wg and dispatch/combine cancel exactly).
//
// Harness compiles via compute_103 (no 'a') -> tcgen05 unavailable; using
// family-portable mma.sync.m16n8k16.f16 + cp.async.
//
// Round-7 ncu: tensor=52%, occ=22% (1 CTA/SM), DRAM=2%, L2=26% ->
// latency/occupancy-bound, NOT memory-bound. This round:
//   * fp16 2-term split: C = Ah*Bh + Al*Bh  (A = fp16 hi+lo, B = fp16).
//     Error driver = B fp16 quantization ~2^-12 RMS -> rel_err ~3e-4.
//     33% fewer MMAs, 25% less smem/stage, B-lo loads eliminated.
//   * __launch_bounds__(256,2): 2 CTAs/SM for latency hiding.
//   * GEMM2 BM=64 -> 256 CTAs (128 CTAs left 20 SMs idle, no overlap).
//   * MMA 2-pass order (all hi*hi, then all lo*hi): acc reuse distance 16.
// ============================================================================

// ---------------- scratch ----------------
__device__ __half g_xh[2048 * 1024];
__device__ __half g_xl[2048 * 1024];
__device__ __half g_w1h[4096 * 1024];   // w1^T [DFF, D] fp16
__device__ __half g_w2h[1024 * 4096];   // w2^T [D, DFF] fp16
__device__ __half g_Hh[2048 * 4096];
__device__ __half g_Hl[2048 * 4096];

// ---------------- helpers ----------------
__device__ __forceinline__ void cp_async16(uint32_t s, const void* g) {
    asm volatile("cp.async.cg.shared.global [%0], [%1], 16;" :: "r"(s), "l"(g));
}
__device__ __forceinline__ void mma_f16(float* acc, const uint32_t a[4],
                                        const uint32_t b[2]) {
    asm volatile(
        "mma.sync.aligned.m16n8k16.row.col.f32.f16.f16.f32 "
        "{%0,%1,%2,%3}, {%4,%5,%6,%7}, {%8,%9}, {%0,%1,%2,%3};"
        : "+f"(acc[0]), "+f"(acc[1]), "+f"(acc[2]), "+f"(acc[3])
        : "r"(a[0]), "r"(a[1]), "r"(a[2]), "r"(a[3]),
          "r"(b[0]), "r"(b[1]));
}

// ---------------- prep kernels ----------------
// x fp32 -> fp16 hi + fp16 lo (residual)
__global__ void split_x(const float4* __restrict__ src,
                        __half2* __restrict__ hi,
                        __half2* __restrict__ lo, int n4) {
    int i = blockIdx.x * blockDim.x + threadIdx.x;
    if (i >= n4) return;
    float4 v = src[i];
    __half2 h0 = __floats2half2_rn(v.x, v.y);
    __half2 h1 = __floats2half2_rn(v.z, v.w);
    __half2 l0 = __floats2half2_rn(v.x - __low2float(h0), v.y - __high2float(h0));
    __half2 l1 = __floats2half2_rn(v.z - __low2float(h1), v.w - __high2float(h1));
    hi[2 * i] = h0; hi[2 * i + 1] = h1;
    lo[2 * i] = l0; lo[2 * i + 1] = l1;
}

// W [K,N] fp32 row-major -> T [N,K] fp16 row-major
__global__ void transpose_h(const float* __restrict__ W,
                            __half* __restrict__ Th, int K, int N) {
    __shared__ float t[32][33];
    int x = blockIdx.x * 32 + threadIdx.x;   // N index
    int y = blockIdx.y * 32 + threadIdx.y;   // K index
    #pragma unroll
    for (int j = 0; j < 32; j += 8)
        t[threadIdx.y + j][threadIdx.x] = W[(size_t)(y + j) * N + x];
    __syncthreads();
    int x2 = blockIdx.y * 32 + threadIdx.x;  // K index (out)
    int y2 = blockIdx.x * 32 + threadIdx.y;  // N index (out)
    #pragma unroll
    for (int j = 0; j < 32; j += 8)
        Th[(size_t)(y2 + j) * K + x2] = __float2half_rn(t[threadIdx.x][threadIdx.y + j]);
}

// ---------------- mma.sync GEMM ----------------
// D[m][n] = sum_k A[m][k]*B[n][k]; A fp16 hi/lo [M,K], B fp16 [N,K], K-major.
// SPLIT_OUT: relu + write fp16 hi/lo (GEMM1). else: write fp32 (GEMM2).
template <int BM, bool SPLIT_OUT>
__global__ void __launch_bounds__(256, 2)
gemm_hmma(const __half* __restrict__ Ah, const __half* __restrict__ Al,
          const __half* __restrict__ Bh,
          int K, int ldo,
          float* __restrict__ outF,
          __half* __restrict__ outH, __half* __restrict__ outL)
{
    constexpr int BN = 128;
    constexpr int BK = 32;
    constexpr int ROWB = 80;                 // 64B data + 16B pad per row
    constexpr int A_BYTES = BM * ROWB;
    constexpr int B_BYTES = BN * ROWB;
    constexpr int STAGE = 2 * A_BYTES + B_BYTES;
    constexpr int MI = BM / 32;              // m16 sub-tiles per warp (M)

    extern __shared__ char smem[];
    uint32_t sb;
    asm("{ .reg .u64 t; cvta.to.shared.u64 t, %1; cvt.u32.u64 %0, t; }"
        : "=r"(sb) : "l"(smem));
    const int tid  = threadIdx.x;
    const int lane = tid & 31;
    const int warp = tid >> 5;
    const int wm = (warp & 1) * (BM / 2);    // 2 warps in M
    const int wn = (warp >> 1) * 32;         // 4 warps in N
    const int brow = blockIdx.y * BM;
    const int bcol = blockIdx.x * BN;
    const int KT = K / BK;

    float acc[MI][4][4];
    #pragma unroll
    for (int mi = 0; mi < MI; ++mi)
        #pragma unroll
        for (int ni = 0; ni < 4; ++ni)
            #pragma unroll
            for (int r = 0; r < 4; ++r)
                acc[mi][ni][r] = 0.0f;

    auto load_stage = [&](int kt, int buf) {
        const int k0 = kt * BK;
        const uint32_t s0 = sb + buf * STAGE;
        // A: BM rows x 4 chunks of 16B (8 fp16) x {hi, lo}
        #pragma unroll
        for (int i = 0; i < (BM * 4) / 256; ++i) {
            int id = tid + i * 256;
            int r = id >> 2, c = id & 3;
            uint32_t so = (uint32_t)(r * ROWB + c * 16);
            size_t go = (size_t)(brow + r) * K + k0 + c * 8;
            cp_async16(s0 + so,           Ah + go);
            cp_async16(s0 + A_BYTES + so, Al + go);
        }
        // B: BN rows x 4 chunks (hi only)
        #pragma unroll
        for (int i = 0; i < (BN * 4) / 256; ++i) {
            int id = tid + i * 256;
            int r = id >> 2, c = id & 3;
            uint32_t so = (uint32_t)(2 * A_BYTES + r * ROWB + c * 16);
            size_t go = (size_t)(bcol + r) * K + k0 + c * 8;
            cp_async16(s0 + so, Bh + go);
        }
        asm volatile("cp.async.commit_group;");
    };

    auto compute = [&](int buf) {
        const char* sa_h = smem + buf * STAGE;
        const char* sa_l = sa_h + A_BYTES;
        const char* sb_h = sa_h + 2 * A_BYTES;
        #pragma unroll
        for (int ks = 0; ks < 2; ++ks) {     // two k16 chunks per BK=32
            const int cbyte = (ks * 16 + (lane & 3) * 2) * 2;
            uint32_t ah[MI][4], al[MI][4];
            #pragma unroll
            for (int mi = 0; mi < MI; ++mi) {
                int base = (wm + mi * 16 + (lane >> 2)) * ROWB + cbyte;
                ah[mi][0] = *(const uint32_t*)(sa_h + base);
                ah[mi][1] = *(const uint32_t*)(sa_h + base + 8 * ROWB);
                ah[mi][2] = *(const uint32_t*)(sa_h + base + 16);
                ah[mi][3] = *(const uint32_t*)(sa_h + base + 8 * ROWB + 16);
                al[mi][0] = *(const uint32_t*)(sa_l + base);
                al[mi][1] = *(const uint32_t*)(sa_l + base + 8 * ROWB);
                al[mi][2] = *(const uint32_t*)(sa_l + base + 16);
                al[mi][3] = *(const uint32_t*)(sa_l + base + 8 * ROWB + 16);
            }
            uint32_t bh[4][2];
            #pragma unroll
            for (int ni = 0; ni < 4; ++ni) {
                int base = (wn + ni * 8 + (lane >> 2)) * ROWB + cbyte;
                bh[ni][0] = *(const uint32_t*)(sb_h + base);
                bh[ni][1] = *(const uint32_t*)(sb_h + base + 16);
            }
            // pass 1: hi*hi -- acc reuse distance = MI*4 mmas
            #pragma unroll
            for (int mi = 0; mi < MI; ++mi)
                #pragma unroll
                for (int ni = 0; ni < 4; ++ni)
                    mma_f16(acc[mi][ni], ah[mi], bh[ni]);
            // pass 2: lo*hi
            #pragma unroll
            for (int mi = 0; mi < MI; ++mi)
                #pragma unroll
                for (int ni = 0; ni < 4; ++ni)
                    mma_f16(acc[mi][ni], al[mi], bh[ni]);
        }
    };

    load_stage(0, 0);
    for (int kt = 0; kt < KT; ++kt) {
        const int buf = kt & 1;
        if (kt + 1 < KT) {
            load_stage(kt + 1, buf ^ 1);
            asm volatile("cp.async.wait_group 1;");
        } else {
            asm volatile("cp.async.wait_group 0;");
        }
        __syncthreads();
        compute(buf);
        __syncthreads();
    }

    // Epilogue
    #pragma unroll
    for (int mi = 0; mi < MI; ++mi) {
        int r0 = brow + wm + mi * 16 + (lane >> 2);
        #pragma unroll
        for (int ni = 0; ni < 4; ++ni) {
            int c0 = bcol + wn + ni * 8 + (lane & 3) * 2;
            if (SPLIT_OUT) {
                float v0 = fmaxf(acc[mi][ni][0], 0.0f);
                float v1 = fmaxf(acc[mi][ni][1], 0.0f);
                float v2 = fmaxf(acc[mi][ni][2], 0.0f);
                float v3 = fmaxf(acc[mi][ni][3], 0.0f);
                __half2 h01 = __floats2half2_rn(v0, v1);
                __half2 l01 = __floats2half2_rn(v0 - __low2float(h01),
                                                v1 - __high2float(h01));
                __half2 h23 = __floats2half2_rn(v2, v3);
                __half2 l23 = __floats2half2_rn(v2 - __low2float(h23),
                                                v3 - __high2float(h23));
                *(__half2*)(outH + (size_t)r0 * ldo + c0)       = h01;
                *(__half2*)(outL + (size_t)r0 * ldo + c0)       = l01;
                *(__half2*)(outH + (size_t)(r0 + 8) * ldo + c0) = h23;
                *(__half2*)(outL + (size_t)(r0 + 8) * ldo + c0) = l23;
            } else {
                float2 u0, u1;
                u0.x = acc[mi][ni][0]; u0.y = acc[mi][ni][1];
                u1.x = acc[mi][ni][2]; u1.y = acc[mi][ni][3];
                *(float2*)(outF + (size_t)r0 * ldo + c0)       = u0;
                *(float2*)(outF + (size_t)(r0 + 8) * ldo + c0) = u1;
            }
        }
    }
}

// ---------------- launch ----------------
extern "C" void kernel_launch(void* const* d_in, const int* in_sizes, int n_in,
                              void* d_out, int out_size) {
    (void)in_sizes; (void)n_in; (void)out_size;
    const float* x  = (const float*)d_in[0];
    // d_in[1] = Wg -- unused: routing cancels (normalized top-2 gates sum to 1)
    const float* w1 = (const float*)d_in[2];
    const float* w2 = (const float*)d_in[3];
    float* out = (float*)d_out;

    const int M = 2048, D = 1024, DFF = 4096;

    __half *xh, *xl, *w1h, *w2h, *Hh, *Hl;
    { void* p; cudaGetSymbolAddress(&p, g_xh);  xh  = (__half*)p; }
    { void* p; cudaGetSymbolAddress(&p, g_xl);  xl  = (__half*)p; }
    { void* p; cudaGetSymbolAddress(&p, g_w1h); w1h = (__half*)p; }
    { void* p; cudaGetSymbolAddress(&p, g_w2h); w2h = (__half*)p; }
    { void* p; cudaGetSymbolAddress(&p, g_Hh);  Hh  = (__half*)p; }
    { void* p; cudaGetSymbolAddress(&p, g_Hl);  Hl  = (__half*)p; }

    // smem: 2 stages; stage = (2*BM + 128) * 80 bytes
    const int smem1 = 2 * ((2 * 128 + 128) * 80);  // 61440 (BM=128)
    const int smem2 = 2 * ((2 * 64 + 128) * 80);   // 40960 (BM=64)
    cudaFuncSetAttribute(gemm_hmma<128, true>,
                         cudaFuncAttributeMaxDynamicSharedMemorySize, smem1);
    cudaFuncSetAttribute(gemm_hmma<64, false>,
                         cudaFuncAttributeMaxDynamicSharedMemorySize, smem2);

    // prep
    split_x<<<(M * D / 4 + 255) / 256, 256>>>(
        (const float4*)x, (__half2*)xh, (__half2*)xl, M * D / 4);
    transpose_h<<<dim3(DFF / 32, D / 32), dim3(32, 8)>>>(w1, w1h, D, DFF);
    transpose_h<<<dim3(D / 32, DFF / 32), dim3(32, 8)>>>(w2, w2h, DFF, D);

    // GEMM1: H = relu(x @ w1) -> fp16 hi/lo [2048, 4096], tiles 128x128 (512 CTAs)
    gemm_hmma<128, true><<<dim3(DFF / 128, M / 128), 256, smem1>>>(
        xh, xl, w1h, D, DFF, nullptr, Hh, Hl);
    // GEMM2: out = H @ w2 -> fp32 [2048, 1024], tiles 64x128 (256 CTAs)
    gemm_hmma<64, false><<<dim3(D / 128, M / 64), 256, smem2>>>(
        Hh, Hl, w2h, DFF, D, out, nullptr, nullptr);
}

// round 14
// speedup vs baseline: 1.3747x; 1.0449x over previous
#include <cuda_runtime.h>
#include <cuda_fp16.h>
#include <cstdint>

// ============================================================================
// MoE layer collapses to: out = relu(x @ w1) @ w2
// (w1/w2 shared across experts, capacity=S so no drops, normalized top-2
//  gates sum to 1 -> Wg and dispatch/combine cancel exactly).
//
// Harness compiles via compute_103 (no 'a') -> tcgen05 unavailable.
// Family-portable path: mma.sync.m16n8k16.f16 + cp.async + ldmatrix.
//
// Round-9 ncu: tensor=44.6%, occ=22% (~2 CTA/SM already), DRAM=1.7% ->
// bound by per-iteration serialization (2 barriers + 96 LDS/warp per BK=32).
// This round (audited 5x, resubmitted through broker timeouts):
//   * ldmatrix.x4 fragment loads: 48 -> 10 shared-load instrs per warp/ks.
//   * 3-stage cp.async pipeline, ONE __syncthreads per iteration
//     (stage kt+2 == stage kt-1 mod 3; top barrier protects overwrite).
//   * Math unchanged: fp16 2-term split C = Ah*Bh + Al*Bh, rel_err 2.95e-4.
// ============================================================================

// ---------------- scratch ----------------
__device__ __half g_xh[2048 * 1024];
__device__ __half g_xl[2048 * 1024];
__device__ __half g_w1h[4096 * 1024];   // w1^T [DFF, D] fp16
__device__ __half g_w2h[1024 * 4096];   // w2^T [D, DFF] fp16
__device__ __half g_Hh[2048 * 4096];
__device__ __half g_Hl[2048 * 4096];

// ---------------- helpers ----------------
__device__ __forceinline__ void cp_async16(uint32_t s, const void* g) {
    asm volatile("cp.async.cg.shared.global [%0], [%1], 16;" :: "r"(s), "l"(g));
}
__device__ __forceinline__ void ldsm_x4(uint32_t* r, uint32_t addr) {
    asm volatile("ldmatrix.sync.aligned.m8n8.x4.shared.b16 {%0,%1,%2,%3}, [%4];"
                 : "=r"(r[0]), "=r"(r[1]), "=r"(r[2]), "=r"(r[3]) : "r"(addr));
}
__device__ __forceinline__ void mma_f16(float* acc, const uint32_t a[4],
                                        const uint32_t b[2]) {
    asm volatile(
        "mma.sync.aligned.m16n8k16.row.col.f32.f16.f16.f32 "
        "{%0,%1,%2,%3}, {%4,%5,%6,%7}, {%8,%9}, {%0,%1,%2,%3};"
        : "+f"(acc[0]), "+f"(acc[1]), "+f"(acc[2]), "+f"(acc[3])
        : "r"(a[0]), "r"(a[1]), "r"(a[2]), "r"(a[3]),
          "r"(b[0]), "r"(b[1]));
}

// ---------------- prep kernels ----------------
__global__ void split_x(const float4* __restrict__ src,
                        __half2* __restrict__ hi,
                        __half2* __restrict__ lo, int n4) {
    int i = blockIdx.x * blockDim.x + threadIdx.x;
    if (i >= n4) return;
    float4 v = src[i];
    __half2 h0 = __floats2half2_rn(v.x, v.y);
    __half2 h1 = __floats2half2_rn(v.z, v.w);
    __half2 l0 = __floats2half2_rn(v.x - __low2float(h0), v.y - __high2float(h0));
    __half2 l1 = __floats2half2_rn(v.z - __low2float(h1), v.w - __high2float(h1));
    hi[2 * i] = h0; hi[2 * i + 1] = h1;
    lo[2 * i] = l0; lo[2 * i + 1] = l1;
}

// W [K,N] fp32 row-major -> T [N,K] fp16 row-major
__global__ void transpose_h(const float* __restrict__ W,
                            __half* __restrict__ Th, int K, int N) {
    __shared__ float t[32][33];
    int x = blockIdx.x * 32 + threadIdx.x;   // N index
    int y = blockIdx.y * 32 + threadIdx.y;   // K index
    #pragma unroll
    for (int j = 0; j < 32; j += 8)
        t[threadIdx.y + j][threadIdx.x] = W[(size_t)(y + j) * N + x];
    __syncthreads();
    int x2 = blockIdx.y * 32 + threadIdx.x;  // K index (out)
    int y2 = blockIdx.x * 32 + threadIdx.y;  // N index (out)
    #pragma unroll
    for (int j = 0; j < 32; j += 8)
        Th[(size_t)(y2 + j) * K + x2] = __float2half_rn(t[threadIdx.x][threadIdx.y + j]);
}

// ---------------- mma.sync GEMM ----------------
// D[m][n] = sum_k A[m][k]*B[n][k]; A fp16 hi/lo [M,K], B fp16 [N,K], K-major.
template <int BM, bool SPLIT_OUT>
__global__ void __launch_bounds__(256, 2)
gemm_hmma(const __half* __restrict__ Ah, const __half* __restrict__ Al,
          const __half* __restrict__ Bh,
          int K, int ldo,
          float* __restrict__ outF,
          __half* __restrict__ outH, __half* __restrict__ outL)
{
    constexpr int BN = 128;
    constexpr int BK = 32;
    constexpr int NS = 3;                    // pipeline stages
    constexpr int ROWB = 80;                 // 64B data + 16B pad per row
    constexpr int A_BYTES = BM * ROWB;
    constexpr int B_BYTES = BN * ROWB;
    constexpr int STAGE = 2 * A_BYTES + B_BYTES;
    constexpr int MI = BM / 32;              // m16 sub-tiles per warp (M)

    extern __shared__ char smem[];
    uint32_t sb;
    asm("{ .reg .u64 t; cvta.to.shared.u64 t, %1; cvt.u32.u64 %0, t; }"
        : "=r"(sb) : "l"(smem));
    const int tid  = threadIdx.x;
    const int lane = tid & 31;
    const int warp = tid >> 5;
    const int wm = (warp & 1) * (BM / 2);    // 2 warps in M
    const int wn = (warp >> 1) * 32;         // 4 warps in N
    const int brow = blockIdx.y * BM;
    const int bcol = blockIdx.x * BN;
    const int KT = K / BK;

    // ldmatrix per-lane address components (bytes, relative to tile base)
    const int a_off = ((lane & 7) + ((lane >> 3) & 1) * 8) * ROWB
                    + (lane >> 4) * 16;                       // A: 16 rows x 2 col-halves
    const int b_off = ((lane & 7) + ((lane >> 4) & 1) * 8) * ROWB
                    + ((lane >> 3) & 1) * 16;                 // B: 2 n-tiles x 2 col-halves

    float acc[MI][4][4];
    #pragma unroll
    for (int mi = 0; mi < MI; ++mi)
        #pragma unroll
        for (int ni = 0; ni < 4; ++ni)
            #pragma unroll
            for (int r = 0; r < 4; ++r)
                acc[mi][ni][r] = 0.0f;

    auto load_stage = [&](int kt, int buf) {
        const int k0 = kt * BK;
        const uint32_t s0 = sb + buf * STAGE;
        #pragma unroll
        for (int i = 0; i < (BM * 4) / 256; ++i) {
            int id = tid + i * 256;
            int r = id >> 2, c = id & 3;
            uint32_t so = (uint32_t)(r * ROWB + c * 16);
            size_t go = (size_t)(brow + r) * K + k0 + c * 8;
            cp_async16(s0 + so,           Ah + go);
            cp_async16(s0 + A_BYTES + so, Al + go);
        }
        #pragma unroll
        for (int i = 0; i < (BN * 4) / 256; ++i) {
            int id = tid + i * 256;
            int r = id >> 2, c = id & 3;
            uint32_t so = (uint32_t)(2 * A_BYTES + r * ROWB + c * 16);
            size_t go = (size_t)(bcol + r) * K + k0 + c * 8;
            cp_async16(s0 + so, Bh + go);
        }
        asm volatile("cp.async.commit_group;");
    };

    auto compute = [&](int buf) {
        const uint32_t sa_h = sb + buf * STAGE;
        const uint32_t sa_l = sa_h + A_BYTES;
        const uint32_t sb_h = sa_h + 2 * A_BYTES;
        #pragma unroll
        for (int ks = 0; ks < 2; ++ks) {     // two k16 chunks per BK=32
            const int kb = ks * 32;          // byte offset of k-chunk
            uint32_t ah[MI][4], al[MI][4];
            #pragma unroll
            for (int mi = 0; mi < MI; ++mi)
                ldsm_x4(ah[mi], sa_h + (wm + mi * 16) * ROWB + kb + a_off);
            #pragma unroll
            for (int mi = 0; mi < MI; ++mi)
                ldsm_x4(al[mi], sa_l + (wm + mi * 16) * ROWB + kb + a_off);
            uint32_t bt[2][4];               // bt[p] covers ni = 2p, 2p+1
            ldsm_x4(bt[0], sb_h + (wn +  0) * ROWB + kb + b_off);
            ldsm_x4(bt[1], sb_h + (wn + 16) * ROWB + kb + b_off);
            // pass 1: hi*hi
            #pragma unroll
            for (int mi = 0; mi < MI; ++mi)
                #pragma unroll
                for (int ni = 0; ni < 4; ++ni)
                    mma_f16(acc[mi][ni], ah[mi], &bt[ni >> 1][(ni & 1) * 2]);
            // pass 2: lo*hi
            #pragma unroll
            for (int mi = 0; mi < MI; ++mi)
                #pragma unroll
                for (int ni = 0; ni < 4; ++ni)
                    mma_f16(acc[mi][ni], al[mi], &bt[ni >> 1][(ni & 1) * 2]);
        }
    };

    // 3-stage pipeline, one barrier per iteration
    load_stage(0, 0);
    if (KT > 1) load_stage(1, 1);
    for (int kt = 0; kt < KT; ++kt) {
        if (kt + 1 < KT) {
            asm volatile("cp.async.wait_group 1;");
        } else {
            asm volatile("cp.async.wait_group 0;");
        }
        __syncthreads();                     // stage kt visible; all warps done kt-1
        if (kt + 2 < KT) load_stage(kt + 2, (kt + 2) % NS);
        compute(kt % NS);
    }

    // Epilogue
    #pragma unroll
    for (int mi = 0; mi < MI; ++mi) {
        int r0 = brow + wm + mi * 16 + (lane >> 2);
        #pragma unroll
        for (int ni = 0; ni < 4; ++ni) {
            int c0 = bcol + wn + ni * 8 + (lane & 3) * 2;
            if (SPLIT_OUT) {
                float v0 = fmaxf(acc[mi][ni][0], 0.0f);
                float v1 = fmaxf(acc[mi][ni][1], 0.0f);
                float v2 = fmaxf(acc[mi][ni][2], 0.0f);
                float v3 = fmaxf(acc[mi][ni][3], 0.0f);
                __half2 h01 = __floats2half2_rn(v0, v1);
                __half2 l01 = __floats2half2_rn(v0 - __low2float(h01),
                                                v1 - __high2float(h01));
                __half2 h23 = __floats2half2_rn(v2, v3);
                __half2 l23 = __floats2half2_rn(v2 - __low2float(h23),
                                                v3 - __high2float(h23));
                *(__half2*)(outH + (size_t)r0 * ldo + c0)       = h01;
                *(__half2*)(outL + (size_t)r0 * ldo + c0)       = l01;
                *(__half2*)(outH + (size_t)(r0 + 8) * ldo + c0) = h23;
                *(__half2*)(outL + (size_t)(r0 + 8) * ldo + c0) = l23;
            } else {
                float2 u0, u1;
                u0.x = acc[mi][ni][0]; u0.y = acc[mi][ni][1];
                u1.x = acc[mi][ni][2]; u1.y = acc[mi][ni][3];
                *(float2*)(outF + (size_t)r0 * ldo + c0)       = u0;
                *(float2*)(outF + (size_t)(r0 + 8) * ldo + c0) = u1;
            }
        }
    }
}

// ---------------- launch ----------------
extern "C" void kernel_launch(void* const* d_in, const int* in_sizes, int n_in,
                              void* d_out, int out_size) {
    (void)in_sizes; (void)n_in; (void)out_size;
    const float* x  = (const float*)d_in[0];
    // d_in[1] = Wg -- unused: routing cancels (normalized top-2 gates sum to 1)
    const float* w1 = (const float*)d_in[2];
    const float* w2 = (const float*)d_in[3];
    float* out = (float*)d_out;

    const int M = 2048, D = 1024, DFF = 4096;

    __half *xh, *xl, *w1h, *w2h, *Hh, *Hl;
    { void* p; cudaGetSymbolAddress(&p, g_xh);  xh  = (__half*)p; }
    { void* p; cudaGetSymbolAddress(&p, g_xl);  xl  = (__half*)p; }
    { void* p; cudaGetSymbolAddress(&p, g_w1h); w1h = (__half*)p; }
    { void* p; cudaGetSymbolAddress(&p, g_w2h); w2h = (__half*)p; }
    { void* p; cudaGetSymbolAddress(&p, g_Hh);  Hh  = (__half*)p; }
    { void* p; cudaGetSymbolAddress(&p, g_Hl);  Hl  = (__half*)p; }

    // smem: 3 stages; stage = (2*BM + 128) * 80 bytes
    const int smem1 = 3 * ((2 * 128 + 128) * 80);  // 92160 (BM=128)
    const int smem2 = 3 * ((2 * 64 + 128) * 80);   // 61440 (BM=64)
    cudaFuncSetAttribute(gemm_hmma<128, true>,
                         cudaFuncAttributeMaxDynamicSharedMemorySize, smem1);
    cudaFuncSetAttribute(gemm_hmma<64, false>,
                         cudaFuncAttributeMaxDynamicSharedMemorySize, smem2);

    // prep
    split_x<<<(M * D / 4 + 255) / 256, 256>>>(
        (const float4*)x, (__half2*)xh, (__half2*)xl, M * D / 4);
    transpose_h<<<dim3(DFF / 32, D / 32), dim3(32, 8)>>>(w1, w1h, D, DFF);
    transpose_h<<<dim3(D / 32, DFF / 32), dim3(32, 8)>>>(w2, w2h, DFF, D);

    // GEMM1: H = relu(x @ w1) -> fp16 hi/lo [2048, 4096], tiles 128x128 (512 CTAs)
    gemm_hmma<128, true><<<dim3(DFF / 128, M / 128), 256, smem1>>>(
        xh, xl, w1h, D, DFF, nullptr, Hh, Hl);
    // GEMM2: out = H @ w2 -> fp32 [2048, 1024], tiles 64x128 (256 CTAs)
    gemm_hmma<64, false><<<dim3(D / 128, M / 64), 256, smem2>>>(
        Hh, Hl, w2h, DFF, D, out, nullptr, nullptr);
}